// round 12
// baseline (speedup 1.0000x reference)
#include <cuda_runtime.h>
#include <cuda_bf16.h>
#include <cuda_fp16.h>

#define N_NODES 8192
#define NFEAT   256
#define NHID    64
#define NHEADS  4
#define NCLASS  121
#define MAXDEG  256
#define ALPHA_LRELU 0.2f

// ---------------- scratch (static device globals; no allocation) ----------------
__device__ int   g_deg[N_NODES];
__device__ int   g_nbr[N_NODES * MAXDEG];
__device__ uint2 g_Wh_h [N_NODES * 64];       // layer-1 Wh in fp16 (4 halves per uint2)
__device__ float g_fsrc[N_NODES * NHEADS];    // interleaved [node][head]
__device__ float g_fdst[N_NODES * NHEADS];    // interleaved [node][head]
__device__ float g_hcat[N_NODES * 256];
__device__ unsigned g_Wh2h[N_NODES * 64];     // layer-2 Wh in fp16 (2 halves per uint)
__device__ float g_f2srcp[2][N_NODES];        // layer-2 score partials per col-block
__device__ float g_f2dstp[2][N_NODES];

// ------- CSR build: warp per row, ballot compaction, 4-deep load batching -------
__global__ __launch_bounds__(256) void build_csr(const float* __restrict__ adj) {
    int warp = (blockIdx.x * blockDim.x + threadIdx.x) >> 5;
    int lane = threadIdx.x & 31;
    if (warp >= N_NODES) return;
    const float4* row = reinterpret_cast<const float4*>(adj + (size_t)warp * N_NODES);
    int cnt = 0;
    int* out = g_nbr + warp * MAXDEG;
    for (int base = 0; base < N_NODES / 4; base += 128) {
        float4 v[4];
        #pragma unroll
        for (int r = 0; r < 4; r++) v[r] = row[base + r * 32 + lane];
        #pragma unroll
        for (int r = 0; r < 4; r++) {
            float vv[4] = {v[r].x, v[r].y, v[r].z, v[r].w};
            int col0 = (base + r * 32 + lane) * 4;
            #pragma unroll
            for (int q = 0; q < 4; q++) {
                unsigned m = __ballot_sync(0xffffffffu, vv[q] > 0.0f);
                if (vv[q] > 0.0f) {
                    int pos = cnt + __popc(m & ((1u << lane) - 1u));
                    if (pos < MAXDEG) out[pos] = col0 + q;
                }
                cnt += __popc(m);
            }
        }
    }
    if (lane == 0) g_deg[warp] = cnt < MAXDEG ? cnt : MAXDEG;
}

// ------- double-buffered fp32 GEMM: BM=64, BN=64, BK=16, 256 thr, 4x4 -----------
// MODE 0: B(k,c) = Ws[...]; stores fp16 Wh; epilogue computes f1 src/dst scores.
// MODE 1: B(k,c) = W_out (padded on the fly); stores fp16 Wh2; f2 partials.
template <int MODE>
__global__ __launch_bounds__(256) void sgemm6(const float* __restrict__ A,
                                              const float* __restrict__ B,
                                              const float* __restrict__ avec) {
    __shared__ float sA[2][16][68];
    __shared__ float sB[2][16][68];

    int tid = threadIdx.x;
    int m0 = blockIdx.y * 64;
    int c0 = blockIdx.x * 64;

    int ar  = tid >> 2;            // 0..63
    int ac4 = (tid & 3) * 4;       // 0,4,8,12
    int bk  = tid >> 4;            // 0..15
    int bc4 = (tid & 15) * 4;      // 0..60

    int ty = tid >> 4;             // 0..15
    int tx = tid & 15;             // 0..15

    float acc[4][4];
    #pragma unroll
    for (int i = 0; i < 4; i++)
        #pragma unroll
        for (int j = 0; j < 4; j++) acc[i][j] = 0.0f;

    // preload tile 0
    float4 a_n = *reinterpret_cast<const float4*>(A + (size_t)(m0 + ar) * NFEAT + ac4);
    float4 b_n;
    if (MODE == 0) {
        b_n = *reinterpret_cast<const float4*>(
            B + (size_t)(c0 >> 6) * (NFEAT * NHID) + (size_t)bk * NHID + bc4);
    } else {
        float* bb = reinterpret_cast<float*>(&b_n);
        #pragma unroll
        for (int j = 0; j < 4; j++) {
            int c = c0 + bc4 + j;
            bb[j] = (c < NCLASS) ? B[(size_t)bk * NCLASS + c] : 0.0f;
        }
    }
    sA[0][ac4 + 0][ar] = a_n.x;
    sA[0][ac4 + 1][ar] = a_n.y;
    sA[0][ac4 + 2][ar] = a_n.z;
    sA[0][ac4 + 3][ar] = a_n.w;
    sB[0][bk][bc4 + 0] = b_n.x;
    sB[0][bk][bc4 + 1] = b_n.y;
    sB[0][bk][bc4 + 2] = b_n.z;
    sB[0][bk][bc4 + 3] = b_n.w;
    __syncthreads();

    int buf = 0;
    #pragma unroll 1
    for (int t = 0; t < 16; t++) {
        if (t < 15) {
            int k0 = (t + 1) * 16;
            a_n = *reinterpret_cast<const float4*>(A + (size_t)(m0 + ar) * NFEAT + k0 + ac4);
            if (MODE == 0) {
                b_n = *reinterpret_cast<const float4*>(
                    B + (size_t)(c0 >> 6) * (NFEAT * NHID) + (size_t)(k0 + bk) * NHID + bc4);
            } else {
                float* bb = reinterpret_cast<float*>(&b_n);
                #pragma unroll
                for (int j = 0; j < 4; j++) {
                    int c = c0 + bc4 + j;
                    bb[j] = (c < NCLASS) ? B[(size_t)(k0 + bk) * NCLASS + c] : 0.0f;
                }
            }
        }

        #pragma unroll
        for (int kk = 0; kk < 16; kk++) {
            float4 a4 = *reinterpret_cast<const float4*>(&sA[buf][kk][ty * 4]);
            float4 b4 = *reinterpret_cast<const float4*>(&sB[buf][kk][tx * 4]);
            float a[4] = {a4.x, a4.y, a4.z, a4.w};
            float b[4] = {b4.x, b4.y, b4.z, b4.w};
            #pragma unroll
            for (int i = 0; i < 4; i++)
                #pragma unroll
                for (int j = 0; j < 4; j++) acc[i][j] = fmaf(a[i], b[j], acc[i][j]);
        }

        if (t < 15) {
            int nb = buf ^ 1;
            sA[nb][ac4 + 0][ar] = a_n.x;
            sA[nb][ac4 + 1][ar] = a_n.y;
            sA[nb][ac4 + 2][ar] = a_n.z;
            sA[nb][ac4 + 3][ar] = a_n.w;
            sB[nb][bk][bc4 + 0] = b_n.x;
            sB[nb][bk][bc4 + 1] = b_n.y;
            sB[nb][bk][bc4 + 2] = b_n.z;
            sB[nb][bk][bc4 + 3] = b_n.w;
            __syncthreads();
            buf = nb;
        }
    }

    // -------- fp16 stores --------
    #pragma unroll
    for (int i = 0; i < 4; i++) {
        int row = m0 + ty * 4 + i;
        __half2 h01 = __floats2half2_rn(acc[i][0], acc[i][1]);
        __half2 h23 = __floats2half2_rn(acc[i][2], acc[i][3]);
        uint2 u;
        u.x = *reinterpret_cast<unsigned*>(&h01);
        u.y = *reinterpret_cast<unsigned*>(&h23);
        if (MODE == 0) {
            g_Wh_h[(size_t)row * 64 + (c0 >> 2) + tx] = u;
        } else {
            *reinterpret_cast<uint2*>(&g_Wh2h[(size_t)row * 64 + (c0 >> 1) + tx * 2]) = u;
        }
    }

    // -------- fused attention-score epilogue (fp32 acc) --------
    float as[4], ad[4];
    if (MODE == 0) {
        const float* ah = avec + (c0 >> 6) * (2 * NHID);
        #pragma unroll
        for (int j = 0; j < 4; j++) {
            as[j] = ah[tx * 4 + j];
            ad[j] = ah[NHID + tx * 4 + j];
        }
    } else {
        #pragma unroll
        for (int j = 0; j < 4; j++) {
            int c = c0 + tx * 4 + j;
            as[j] = (c < NCLASS) ? avec[c] : 0.0f;
            ad[j] = (c < NCLASS) ? avec[NCLASS + c] : 0.0f;
        }
    }
    #pragma unroll
    for (int i = 0; i < 4; i++) {
        float s = fmaf(acc[i][0], as[0], acc[i][1] * as[1]) +
                  fmaf(acc[i][2], as[2], acc[i][3] * as[3]);
        float d = fmaf(acc[i][0], ad[0], acc[i][1] * ad[1]) +
                  fmaf(acc[i][2], ad[2], acc[i][3] * ad[3]);
        #pragma unroll
        for (int o = 1; o < 16; o <<= 1) {
            s += __shfl_xor_sync(0xffffffffu, s, o);
            d += __shfl_xor_sync(0xffffffffu, d, o);
        }
        if (tx == 0) {
            int row = m0 + ty * 4 + i;
            if (MODE == 0) {
                int h = c0 >> 6;
                g_fsrc[row * 4 + h] = s;
                g_fdst[row * 4 + h] = d;
            } else {
                g_f2srcp[blockIdx.x][row] = s;
                g_f2dstp[blockIdx.x][row] = d;
            }
        }
    }
}

// ---- layer-1 sparse attention + aggregate + ELU (4 nodes/block, fp16 gather) ---
// s_nbr holds pre-scaled element offsets (nbr*64) to kill per-edge IMADs.
__global__ __launch_bounds__(256) void layer1_agg() {
    __shared__ int   s_nbr[4][MAXDEG];     // neighbor * 64 (uint2 elements)
    __shared__ float s_w[4][NHEADS][MAXDEG];
    __shared__ float s_red[4][NHEADS][2];

    int tid  = threadIdx.x;
    int g    = tid >> 6;          // group 0..3
    int lt   = tid & 63;          // lane in group
    int wig  = lt >> 5;           // warp in group 0..1
    int lane = tid & 31;

    int i   = blockIdx.x * 4 + g;
    int deg = g_deg[i];

    for (int t = lt; t < deg; t += 64) s_nbr[g][t] = g_nbr[i * MAXDEG + t] << 6;
    __syncthreads();

    float4 fs = *reinterpret_cast<const float4*>(g_fsrc + (size_t)i * 4);
    float fsrcA[4] = {fs.x, fs.y, fs.z, fs.w};

    float lmax[4] = {-1e30f, -1e30f, -1e30f, -1e30f};
    for (int j = lt; j < deg; j += 64) {
        // fdst index: (nbr*64)>>4 == nbr*4
        float4 fd = *reinterpret_cast<const float4*>(g_fdst + (s_nbr[g][j] >> 4));
        float fdA[4] = {fd.x, fd.y, fd.z, fd.w};
        #pragma unroll
        for (int h = 0; h < 4; h++) {
            float e = fsrcA[h] + fdA[h];
            e = e >= 0.0f ? e : ALPHA_LRELU * e;
            s_w[g][h][j] = e;
            lmax[h] = fmaxf(lmax[h], e);
        }
    }
    #pragma unroll
    for (int h = 0; h < 4; h++) {
        #pragma unroll
        for (int o = 16; o; o >>= 1) lmax[h] = fmaxf(lmax[h], __shfl_xor_sync(0xffffffffu, lmax[h], o));
        if (lane == 0) s_red[g][h][wig] = lmax[h];
    }
    __syncthreads();
    float m[4];
    #pragma unroll
    for (int h = 0; h < 4; h++) m[h] = fmaxf(s_red[g][h][0], s_red[g][h][1]);

    float lsum[4] = {0.0f, 0.0f, 0.0f, 0.0f};
    for (int j = lt; j < deg; j += 64) {
        #pragma unroll
        for (int h = 0; h < 4; h++) {
            float w = __expf(s_w[g][h][j] - m[h]);
            s_w[g][h][j] = w;
            lsum[h] += w;
        }
    }
    __syncthreads();
    #pragma unroll
    for (int h = 0; h < 4; h++) {
        #pragma unroll
        for (int o = 16; o; o >>= 1) lsum[h] += __shfl_xor_sync(0xffffffffu, lsum[h], o);
        if (lane == 0) s_red[g][h][wig] = lsum[h];
    }
    __syncthreads();

    int h2 = lt >> 4;
    float inv = 1.0f / (s_red[g][h2][0] + s_red[g][h2][1]);
    const float* wrow = s_w[g][h2];
    const int*   nrow = s_nbr[g];
    const uint2* whb  = g_Wh_h + lt;       // base + column; per-edge index is pure add

    float4 acc0 = make_float4(0.f, 0.f, 0.f, 0.f);
    float4 acc1 = make_float4(0.f, 0.f, 0.f, 0.f);

    #define L1_STEP(U, W, ACC) {                                               \
        __half2 p0 = *reinterpret_cast<__half2*>(&U.x);                        \
        __half2 p1 = *reinterpret_cast<__half2*>(&U.y);                        \
        float2 f0 = __half22float2(p0);                                        \
        float2 f1 = __half22float2(p1);                                        \
        ACC.x = fmaf(W, f0.x, ACC.x); ACC.y = fmaf(W, f0.y, ACC.y);            \
        ACC.z = fmaf(W, f1.x, ACC.z); ACC.w = fmaf(W, f1.y, ACC.w); }

    int j = 0;
    for (; j + 7 < deg; j += 8) {
        float w0 = wrow[j],     w1 = wrow[j + 1], w2 = wrow[j + 2], w3 = wrow[j + 3];
        float w4 = wrow[j + 4], w5 = wrow[j + 5], w6 = wrow[j + 6], w7 = wrow[j + 7];
        uint2 u0 = whb[nrow[j]];
        uint2 u1 = whb[nrow[j + 1]];
        uint2 u2 = whb[nrow[j + 2]];
        uint2 u3 = whb[nrow[j + 3]];
        uint2 u4 = whb[nrow[j + 4]];
        uint2 u5 = whb[nrow[j + 5]];
        uint2 u6 = whb[nrow[j + 6]];
        uint2 u7 = whb[nrow[j + 7]];
        L1_STEP(u0, w0, acc0); L1_STEP(u1, w1, acc1);
        L1_STEP(u2, w2, acc0); L1_STEP(u3, w3, acc1);
        L1_STEP(u4, w4, acc0); L1_STEP(u5, w5, acc1);
        L1_STEP(u6, w6, acc0); L1_STEP(u7, w7, acc1);
    }
    for (; j < deg; j++) {
        float w0 = wrow[j];
        uint2 u0 = whb[nrow[j]];
        L1_STEP(u0, w0, acc0);
    }
    #undef L1_STEP

    float4 r;
    r.x = (acc0.x + acc1.x) * inv;
    r.y = (acc0.y + acc1.y) * inv;
    r.z = (acc0.z + acc1.z) * inv;
    r.w = (acc0.w + acc1.w) * inv;
    r.x = r.x > 0.0f ? r.x : expm1f(r.x);
    r.y = r.y > 0.0f ? r.y : expm1f(r.y);
    r.z = r.z > 0.0f ? r.z : expm1f(r.z);
    r.w = r.w > 0.0f ? r.w : expm1f(r.w);
    reinterpret_cast<float4*>(g_hcat)[(size_t)i * 64 + lt] = r;
}

// ---- layer-2 sparse attention + aggregate (4 nodes/block, fp16 gather) ---------
__global__ __launch_bounds__(256) void layer2_agg(float* __restrict__ out) {
    __shared__ int   s_nbr[4][MAXDEG];     // neighbor * 64 (unsigned elements)
    __shared__ float s_w[4][MAXDEG];
    __shared__ float s_red[4][2];

    int tid  = threadIdx.x;
    int g    = tid >> 6;
    int lt   = tid & 63;
    int wig  = lt >> 5;
    int lane = tid & 31;

    int i   = blockIdx.x * 4 + g;
    int deg = g_deg[i];

    for (int t = lt; t < deg; t += 64) s_nbr[g][t] = g_nbr[i * MAXDEG + t] << 6;
    __syncthreads();

    float fsrc = g_f2srcp[0][i] + g_f2srcp[1][i];
    float lmax = -1e30f;
    for (int j = lt; j < deg; j += 64) {
        int nb = s_nbr[g][j] >> 6;
        float e = fsrc + g_f2dstp[0][nb] + g_f2dstp[1][nb];
        e = e >= 0.0f ? e : ALPHA_LRELU * e;
        s_w[g][j] = e;
        lmax = fmaxf(lmax, e);
    }
    #pragma unroll
    for (int o = 16; o; o >>= 1) lmax = fmaxf(lmax, __shfl_xor_sync(0xffffffffu, lmax, o));
    if (lane == 0) s_red[g][wig] = lmax;
    __syncthreads();
    float m = fmaxf(s_red[g][0], s_red[g][1]);

    float lsum = 0.0f;
    for (int j = lt; j < deg; j += 64) {
        float w = __expf(s_w[g][j] - m);
        s_w[g][j] = w;
        lsum += w;
    }
    __syncthreads();
    #pragma unroll
    for (int o = 16; o; o >>= 1) lsum += __shfl_xor_sync(0xffffffffu, lsum, o);
    if (lane == 0) s_red[g][wig] = lsum;
    __syncthreads();
    float inv = 1.0f / (s_red[g][0] + s_red[g][1]);

    const float*    wrow = s_w[g];
    const int*      nrow = s_nbr[g];
    const unsigned* whb  = g_Wh2h + lt;    // per-edge index is pure add
    float2 acc0 = make_float2(0.f, 0.f);
    float2 acc1 = make_float2(0.f, 0.f);

    #define L2_STEP(U, W, ACC) {                                               \
        float2 f = __half22float2(*reinterpret_cast<__half2*>(&U));            \
        ACC.x = fmaf(W, f.x, ACC.x); ACC.y = fmaf(W, f.y, ACC.y); }

    int j = 0;
    for (; j + 7 < deg; j += 8) {
        float w0 = wrow[j],     w1 = wrow[j + 1], w2 = wrow[j + 2], w3 = wrow[j + 3];
        float w4 = wrow[j + 4], w5 = wrow[j + 5], w6 = wrow[j + 6], w7 = wrow[j + 7];
        unsigned u0 = whb[nrow[j]];
        unsigned u1 = whb[nrow[j + 1]];
        unsigned u2 = whb[nrow[j + 2]];
        unsigned u3 = whb[nrow[j + 3]];
        unsigned u4 = whb[nrow[j + 4]];
        unsigned u5 = whb[nrow[j + 5]];
        unsigned u6 = whb[nrow[j + 6]];
        unsigned u7 = whb[nrow[j + 7]];
        L2_STEP(u0, w0, acc0); L2_STEP(u1, w1, acc1);
        L2_STEP(u2, w2, acc0); L2_STEP(u3, w3, acc1);
        L2_STEP(u4, w4, acc0); L2_STEP(u5, w5, acc1);
        L2_STEP(u6, w6, acc0); L2_STEP(u7, w7, acc1);
    }
    for (; j < deg; j++) {
        float w0 = wrow[j];
        unsigned u0 = whb[nrow[j]];
        L2_STEP(u0, w0, acc0);
    }
    #undef L2_STEP

    int c = lt * 2;
    if (c < NCLASS)     out[(size_t)i * NCLASS + c]     = (acc0.x + acc1.x) * inv;
    if (c + 1 < NCLASS) out[(size_t)i * NCLASS + c + 1] = (acc0.y + acc1.y) * inv;
}

// ---------------- host launch ---------------------------------------------------
extern "C" void kernel_launch(void* const* d_in, const int* in_sizes, int n_in,
                              void* d_out, int out_size) {
    const float* x       = (const float*)d_in[0];   // [8192, 256]
    const float* adj     = (const float*)d_in[1];   // [8192, 8192]
    const float* Ws      = (const float*)d_in[2];   // [4, 256, 64]
    const float* a_heads = (const float*)d_in[3];   // [4, 128]
    const float* W_out   = (const float*)d_in[4];   // [256, 121]
    const float* a_out   = (const float*)d_in[5];   // [242]
    float* out = (float*)d_out;                     // [8192, 121]

    float* dHcat;
    cudaGetSymbolAddress((void**)&dHcat, g_hcat);

    static cudaStream_t s_side = []() {
        cudaStream_t s; cudaStreamCreateWithFlags(&s, cudaStreamNonBlocking); return s;
    }();
    static cudaEvent_t ev_fork = []() {
        cudaEvent_t e; cudaEventCreateWithFlags(&e, cudaEventDisableTiming); return e;
    }();
    static cudaEvent_t ev_join = []() {
        cudaEvent_t e; cudaEventCreateWithFlags(&e, cudaEventDisableTiming); return e;
    }();

    // fork: CSR build (DRAM-bound) runs concurrently with GEMM1 (FMA-bound)
    cudaEventRecord(ev_fork, 0);
    cudaStreamWaitEvent(s_side, ev_fork, 0);
    build_csr<<<N_NODES / 8, 256, 0, s_side>>>(adj);
    cudaEventRecord(ev_join, s_side);

    // main stream: layer-1 GEMM with fused f1 epilogue + fp16 Wh store
    sgemm6<0><<<dim3(4, N_NODES / 64), 256>>>(x, Ws, a_heads);

    // join: aggregation needs both CSR and scores
    cudaStreamWaitEvent(0, ev_join, 0);
    layer1_agg<<<N_NODES / 4, 256>>>();

    // layer 2: GEMM with fused f2-partials epilogue + fp16 Wh2 store, then aggregate
    sgemm6<1><<<dim3(2, N_NODES / 64), 256>>>(dHcat, W_out, a_out);
    layer2_agg<<<N_NODES / 4, 256>>>(out);
}

// round 13
// speedup vs baseline: 1.3802x; 1.3802x over previous
#include <cuda_runtime.h>
#include <cuda_bf16.h>
#include <cuda_fp16.h>

#define N_NODES 8192
#define NFEAT   256
#define NHID    64
#define NHEADS  4
#define NCLASS  121
#define MAXDEG  256
#define ALPHA_LRELU 0.2f

// ---------------- scratch (static device globals; no allocation) ----------------
__device__ int   g_deg[N_NODES];
__device__ int   g_nbr[N_NODES * MAXDEG];
__device__ uint2 g_Wh_h [N_NODES * 64];       // layer-1 Wh in fp16 (4 halves per uint2)
__device__ float g_fsrc[N_NODES * NHEADS];    // interleaved [node][head]
__device__ float g_fdst[N_NODES * NHEADS];    // interleaved [node][head]
__device__ float g_hcat[N_NODES * 256];
__device__ unsigned g_Wh2h[N_NODES * 64];     // layer-2 Wh in fp16 (2 halves per uint)
__device__ float g_f2srcp[2][N_NODES];        // layer-2 score partials per col-block
__device__ float g_f2dstp[2][N_NODES];

// ------- CSR build: warp per row, ballot compaction, 4-deep load batching -------
__global__ __launch_bounds__(256) void build_csr(const float* __restrict__ adj) {
    int warp = (blockIdx.x * blockDim.x + threadIdx.x) >> 5;
    int lane = threadIdx.x & 31;
    if (warp >= N_NODES) return;
    const float4* row = reinterpret_cast<const float4*>(adj + (size_t)warp * N_NODES);
    int cnt = 0;
    int* out = g_nbr + warp * MAXDEG;
    for (int base = 0; base < N_NODES / 4; base += 128) {
        float4 v[4];
        #pragma unroll
        for (int r = 0; r < 4; r++) v[r] = row[base + r * 32 + lane];
        #pragma unroll
        for (int r = 0; r < 4; r++) {
            float vv[4] = {v[r].x, v[r].y, v[r].z, v[r].w};
            int col0 = (base + r * 32 + lane) * 4;
            #pragma unroll
            for (int q = 0; q < 4; q++) {
                unsigned m = __ballot_sync(0xffffffffu, vv[q] > 0.0f);
                if (vv[q] > 0.0f) {
                    int pos = cnt + __popc(m & ((1u << lane) - 1u));
                    if (pos < MAXDEG) out[pos] = col0 + q;
                }
                cnt += __popc(m);
            }
        }
    }
    if (lane == 0) g_deg[warp] = cnt < MAXDEG ? cnt : MAXDEG;
}

// ------- double-buffered fp32 GEMM: BM=64, BN=64, BK=16, 256 thr, 4x4 -----------
// MODE 0: B(k,c) = Ws[...]; stores fp16 Wh; epilogue computes f1 src/dst scores.
// MODE 1: B(k,c) = W_out (padded on the fly); stores fp16 Wh2; f2 partials.
template <int MODE>
__global__ __launch_bounds__(256) void sgemm6(const float* __restrict__ A,
                                              const float* __restrict__ B,
                                              const float* __restrict__ avec) {
    __shared__ float sA[2][16][68];
    __shared__ float sB[2][16][68];

    int tid = threadIdx.x;
    int m0 = blockIdx.y * 64;
    int c0 = blockIdx.x * 64;

    int ar  = tid >> 2;            // 0..63
    int ac4 = (tid & 3) * 4;       // 0,4,8,12
    int bk  = tid >> 4;            // 0..15
    int bc4 = (tid & 15) * 4;      // 0..60

    int ty = tid >> 4;             // 0..15
    int tx = tid & 15;             // 0..15

    float acc[4][4];
    #pragma unroll
    for (int i = 0; i < 4; i++)
        #pragma unroll
        for (int j = 0; j < 4; j++) acc[i][j] = 0.0f;

    // preload tile 0
    float4 a_n = *reinterpret_cast<const float4*>(A + (size_t)(m0 + ar) * NFEAT + ac4);
    float4 b_n;
    if (MODE == 0) {
        b_n = *reinterpret_cast<const float4*>(
            B + (size_t)(c0 >> 6) * (NFEAT * NHID) + (size_t)bk * NHID + bc4);
    } else {
        float* bb = reinterpret_cast<float*>(&b_n);
        #pragma unroll
        for (int j = 0; j < 4; j++) {
            int c = c0 + bc4 + j;
            bb[j] = (c < NCLASS) ? B[(size_t)bk * NCLASS + c] : 0.0f;
        }
    }
    sA[0][ac4 + 0][ar] = a_n.x;
    sA[0][ac4 + 1][ar] = a_n.y;
    sA[0][ac4 + 2][ar] = a_n.z;
    sA[0][ac4 + 3][ar] = a_n.w;
    sB[0][bk][bc4 + 0] = b_n.x;
    sB[0][bk][bc4 + 1] = b_n.y;
    sB[0][bk][bc4 + 2] = b_n.z;
    sB[0][bk][bc4 + 3] = b_n.w;
    __syncthreads();

    int buf = 0;
    #pragma unroll 1
    for (int t = 0; t < 16; t++) {
        if (t < 15) {
            int k0 = (t + 1) * 16;
            a_n = *reinterpret_cast<const float4*>(A + (size_t)(m0 + ar) * NFEAT + k0 + ac4);
            if (MODE == 0) {
                b_n = *reinterpret_cast<const float4*>(
                    B + (size_t)(c0 >> 6) * (NFEAT * NHID) + (size_t)(k0 + bk) * NHID + bc4);
            } else {
                float* bb = reinterpret_cast<float*>(&b_n);
                #pragma unroll
                for (int j = 0; j < 4; j++) {
                    int c = c0 + bc4 + j;
                    bb[j] = (c < NCLASS) ? B[(size_t)(k0 + bk) * NCLASS + c] : 0.0f;
                }
            }
        }

        #pragma unroll
        for (int kk = 0; kk < 16; kk++) {
            float4 a4 = *reinterpret_cast<const float4*>(&sA[buf][kk][ty * 4]);
            float4 b4 = *reinterpret_cast<const float4*>(&sB[buf][kk][tx * 4]);
            float a[4] = {a4.x, a4.y, a4.z, a4.w};
            float b[4] = {b4.x, b4.y, b4.z, b4.w};
            #pragma unroll
            for (int i = 0; i < 4; i++)
                #pragma unroll
                for (int j = 0; j < 4; j++) acc[i][j] = fmaf(a[i], b[j], acc[i][j]);
        }

        if (t < 15) {
            int nb = buf ^ 1;
            sA[nb][ac4 + 0][ar] = a_n.x;
            sA[nb][ac4 + 1][ar] = a_n.y;
            sA[nb][ac4 + 2][ar] = a_n.z;
            sA[nb][ac4 + 3][ar] = a_n.w;
            sB[nb][bk][bc4 + 0] = b_n.x;
            sB[nb][bk][bc4 + 1] = b_n.y;
            sB[nb][bk][bc4 + 2] = b_n.z;
            sB[nb][bk][bc4 + 3] = b_n.w;
            __syncthreads();
            buf = nb;
        }
    }

    // -------- fp16 stores --------
    #pragma unroll
    for (int i = 0; i < 4; i++) {
        int row = m0 + ty * 4 + i;
        __half2 h01 = __floats2half2_rn(acc[i][0], acc[i][1]);
        __half2 h23 = __floats2half2_rn(acc[i][2], acc[i][3]);
        uint2 u;
        u.x = *reinterpret_cast<unsigned*>(&h01);
        u.y = *reinterpret_cast<unsigned*>(&h23);
        if (MODE == 0) {
            g_Wh_h[(size_t)row * 64 + (c0 >> 2) + tx] = u;
        } else {
            *reinterpret_cast<uint2*>(&g_Wh2h[(size_t)row * 64 + (c0 >> 1) + tx * 2]) = u;
        }
    }

    // -------- fused attention-score epilogue (fp32 acc) --------
    float as[4], ad[4];
    if (MODE == 0) {
        const float* ah = avec + (c0 >> 6) * (2 * NHID);
        #pragma unroll
        for (int j = 0; j < 4; j++) {
            as[j] = ah[tx * 4 + j];
            ad[j] = ah[NHID + tx * 4 + j];
        }
    } else {
        #pragma unroll
        for (int j = 0; j < 4; j++) {
            int c = c0 + tx * 4 + j;
            as[j] = (c < NCLASS) ? avec[c] : 0.0f;
            ad[j] = (c < NCLASS) ? avec[NCLASS + c] : 0.0f;
        }
    }
    #pragma unroll
    for (int i = 0; i < 4; i++) {
        float s = fmaf(acc[i][0], as[0], acc[i][1] * as[1]) +
                  fmaf(acc[i][2], as[2], acc[i][3] * as[3]);
        float d = fmaf(acc[i][0], ad[0], acc[i][1] * ad[1]) +
                  fmaf(acc[i][2], ad[2], acc[i][3] * ad[3]);
        #pragma unroll
        for (int o = 1; o < 16; o <<= 1) {
            s += __shfl_xor_sync(0xffffffffu, s, o);
            d += __shfl_xor_sync(0xffffffffu, d, o);
        }
        if (tx == 0) {
            int row = m0 + ty * 4 + i;
            if (MODE == 0) {
                int h = c0 >> 6;
                g_fsrc[row * 4 + h] = s;
                g_fdst[row * 4 + h] = d;
            } else {
                g_f2srcp[blockIdx.x][row] = s;
                g_f2dstp[blockIdx.x][row] = d;
            }
        }
    }
}

// ---- layer-1 sparse attention + aggregate + ELU (4 nodes/block, fp16 gather) ---
__global__ __launch_bounds__(256) void layer1_agg() {
    __shared__ int   s_nbr[4][MAXDEG];
    __shared__ float s_w[4][NHEADS][MAXDEG];
    __shared__ float s_red[4][NHEADS][2];

    int tid  = threadIdx.x;
    int g    = tid >> 6;          // group 0..3
    int lt   = tid & 63;          // lane in group
    int wig  = lt >> 5;           // warp in group 0..1
    int lane = tid & 31;

    int i   = blockIdx.x * 4 + g;
    int deg = g_deg[i];

    for (int t = lt; t < deg; t += 64) s_nbr[g][t] = g_nbr[i * MAXDEG + t];
    __syncthreads();

    float4 fs = *reinterpret_cast<const float4*>(g_fsrc + (size_t)i * 4);
    float fsrcA[4] = {fs.x, fs.y, fs.z, fs.w};

    float lmax[4] = {-1e30f, -1e30f, -1e30f, -1e30f};
    for (int j = lt; j < deg; j += 64) {
        float4 fd = *reinterpret_cast<const float4*>(g_fdst + (size_t)s_nbr[g][j] * 4);
        float fdA[4] = {fd.x, fd.y, fd.z, fd.w};
        #pragma unroll
        for (int h = 0; h < 4; h++) {
            float e = fsrcA[h] + fdA[h];
            e = e >= 0.0f ? e : ALPHA_LRELU * e;
            s_w[g][h][j] = e;
            lmax[h] = fmaxf(lmax[h], e);
        }
    }
    #pragma unroll
    for (int h = 0; h < 4; h++) {
        #pragma unroll
        for (int o = 16; o; o >>= 1) lmax[h] = fmaxf(lmax[h], __shfl_xor_sync(0xffffffffu, lmax[h], o));
        if (lane == 0) s_red[g][h][wig] = lmax[h];
    }
    __syncthreads();
    float m[4];
    #pragma unroll
    for (int h = 0; h < 4; h++) m[h] = fmaxf(s_red[g][h][0], s_red[g][h][1]);

    float lsum[4] = {0.0f, 0.0f, 0.0f, 0.0f};
    for (int j = lt; j < deg; j += 64) {
        #pragma unroll
        for (int h = 0; h < 4; h++) {
            float w = __expf(s_w[g][h][j] - m[h]);
            s_w[g][h][j] = w;
            lsum[h] += w;
        }
    }
    __syncthreads();
    #pragma unroll
    for (int h = 0; h < 4; h++) {
        #pragma unroll
        for (int o = 16; o; o >>= 1) lsum[h] += __shfl_xor_sync(0xffffffffu, lsum[h], o);
        if (lane == 0) s_red[g][h][wig] = lsum[h];
    }
    __syncthreads();

    int h2 = lt >> 4;
    float inv = 1.0f / (s_red[g][h2][0] + s_red[g][h2][1]);
    const float* wrow = s_w[g][h2];
    const int*   nrow = s_nbr[g];

    float4 acc0 = make_float4(0.f, 0.f, 0.f, 0.f);
    float4 acc1 = make_float4(0.f, 0.f, 0.f, 0.f);

    #define L1_STEP(U, W, ACC) {                                               \
        __half2 p0 = *reinterpret_cast<__half2*>(&U.x);                        \
        __half2 p1 = *reinterpret_cast<__half2*>(&U.y);                        \
        float2 f0 = __half22float2(p0);                                        \
        float2 f1 = __half22float2(p1);                                        \
        ACC.x = fmaf(W, f0.x, ACC.x); ACC.y = fmaf(W, f0.y, ACC.y);            \
        ACC.z = fmaf(W, f1.x, ACC.z); ACC.w = fmaf(W, f1.y, ACC.w); }

    int j = 0;
    for (; j + 7 < deg; j += 8) {
        float w0 = wrow[j],     w1 = wrow[j + 1], w2 = wrow[j + 2], w3 = wrow[j + 3];
        float w4 = wrow[j + 4], w5 = wrow[j + 5], w6 = wrow[j + 6], w7 = wrow[j + 7];
        uint2 u0 = g_Wh_h[(size_t)nrow[j]     * 64 + lt];
        uint2 u1 = g_Wh_h[(size_t)nrow[j + 1] * 64 + lt];
        uint2 u2 = g_Wh_h[(size_t)nrow[j + 2] * 64 + lt];
        uint2 u3 = g_Wh_h[(size_t)nrow[j + 3] * 64 + lt];
        uint2 u4 = g_Wh_h[(size_t)nrow[j + 4] * 64 + lt];
        uint2 u5 = g_Wh_h[(size_t)nrow[j + 5] * 64 + lt];
        uint2 u6 = g_Wh_h[(size_t)nrow[j + 6] * 64 + lt];
        uint2 u7 = g_Wh_h[(size_t)nrow[j + 7] * 64 + lt];
        L1_STEP(u0, w0, acc0); L1_STEP(u1, w1, acc1);
        L1_STEP(u2, w2, acc0); L1_STEP(u3, w3, acc1);
        L1_STEP(u4, w4, acc0); L1_STEP(u5, w5, acc1);
        L1_STEP(u6, w6, acc0); L1_STEP(u7, w7, acc1);
    }
    for (; j < deg; j++) {
        float w0 = wrow[j];
        uint2 u0 = g_Wh_h[(size_t)nrow[j] * 64 + lt];
        L1_STEP(u0, w0, acc0);
    }
    #undef L1_STEP

    float4 r;
    r.x = (acc0.x + acc1.x) * inv;
    r.y = (acc0.y + acc1.y) * inv;
    r.z = (acc0.z + acc1.z) * inv;
    r.w = (acc0.w + acc1.w) * inv;
    r.x = r.x > 0.0f ? r.x : expm1f(r.x);
    r.y = r.y > 0.0f ? r.y : expm1f(r.y);
    r.z = r.z > 0.0f ? r.z : expm1f(r.z);
    r.w = r.w > 0.0f ? r.w : expm1f(r.w);
    reinterpret_cast<float4*>(g_hcat)[(size_t)i * 64 + lt] = r;
}

// ---- layer-2 sparse attention + aggregate (4 nodes/block, fp16 gather) ---------
__global__ __launch_bounds__(256) void layer2_agg(float* __restrict__ out) {
    __shared__ int   s_nbr[4][MAXDEG];
    __shared__ float s_w[4][MAXDEG];
    __shared__ float s_red[4][2];

    int tid  = threadIdx.x;
    int g    = tid >> 6;
    int lt   = tid & 63;
    int wig  = lt >> 5;
    int lane = tid & 31;

    int i   = blockIdx.x * 4 + g;
    int deg = g_deg[i];

    for (int t = lt; t < deg; t += 64) s_nbr[g][t] = g_nbr[i * MAXDEG + t];
    __syncthreads();

    float fsrc = g_f2srcp[0][i] + g_f2srcp[1][i];
    float lmax = -1e30f;
    for (int j = lt; j < deg; j += 64) {
        int nb = s_nbr[g][j];
        float e = fsrc + g_f2dstp[0][nb] + g_f2dstp[1][nb];
        e = e >= 0.0f ? e : ALPHA_LRELU * e;
        s_w[g][j] = e;
        lmax = fmaxf(lmax, e);
    }
    #pragma unroll
    for (int o = 16; o; o >>= 1) lmax = fmaxf(lmax, __shfl_xor_sync(0xffffffffu, lmax, o));
    if (lane == 0) s_red[g][wig] = lmax;
    __syncthreads();
    float m = fmaxf(s_red[g][0], s_red[g][1]);

    float lsum = 0.0f;
    for (int j = lt; j < deg; j += 64) {
        float w = __expf(s_w[g][j] - m);
        s_w[g][j] = w;
        lsum += w;
    }
    __syncthreads();
    #pragma unroll
    for (int o = 16; o; o >>= 1) lsum += __shfl_xor_sync(0xffffffffu, lsum, o);
    if (lane == 0) s_red[g][wig] = lsum;
    __syncthreads();
    float inv = 1.0f / (s_red[g][0] + s_red[g][1]);

    const float*  wrow = s_w[g];
    const int*    nrow = s_nbr[g];
    float2 acc0 = make_float2(0.f, 0.f);
    float2 acc1 = make_float2(0.f, 0.f);

    #define L2_STEP(U, W, ACC) {                                               \
        float2 f = __half22float2(*reinterpret_cast<__half2*>(&U));            \
        ACC.x = fmaf(W, f.x, ACC.x); ACC.y = fmaf(W, f.y, ACC.y); }

    int j = 0;
    for (; j + 7 < deg; j += 8) {
        float w0 = wrow[j],     w1 = wrow[j + 1], w2 = wrow[j + 2], w3 = wrow[j + 3];
        float w4 = wrow[j + 4], w5 = wrow[j + 5], w6 = wrow[j + 6], w7 = wrow[j + 7];
        unsigned u0 = g_Wh2h[(size_t)nrow[j]     * 64 + lt];
        unsigned u1 = g_Wh2h[(size_t)nrow[j + 1] * 64 + lt];
        unsigned u2 = g_Wh2h[(size_t)nrow[j + 2] * 64 + lt];
        unsigned u3 = g_Wh2h[(size_t)nrow[j + 3] * 64 + lt];
        unsigned u4 = g_Wh2h[(size_t)nrow[j + 4] * 64 + lt];
        unsigned u5 = g_Wh2h[(size_t)nrow[j + 5] * 64 + lt];
        unsigned u6 = g_Wh2h[(size_t)nrow[j + 6] * 64 + lt];
        unsigned u7 = g_Wh2h[(size_t)nrow[j + 7] * 64 + lt];
        L2_STEP(u0, w0, acc0); L2_STEP(u1, w1, acc1);
        L2_STEP(u2, w2, acc0); L2_STEP(u3, w3, acc1);
        L2_STEP(u4, w4, acc0); L2_STEP(u5, w5, acc1);
        L2_STEP(u6, w6, acc0); L2_STEP(u7, w7, acc1);
    }
    for (; j < deg; j++) {
        float w0 = wrow[j];
        unsigned u0 = g_Wh2h[(size_t)nrow[j] * 64 + lt];
        L2_STEP(u0, w0, acc0);
    }
    #undef L2_STEP

    int c = lt * 2;
    if (c < NCLASS)     out[(size_t)i * NCLASS + c]     = (acc0.x + acc1.x) * inv;
    if (c + 1 < NCLASS) out[(size_t)i * NCLASS + c + 1] = (acc0.y + acc1.y) * inv;
}

// ---------------- host launch ---------------------------------------------------
extern "C" void kernel_launch(void* const* d_in, const int* in_sizes, int n_in,
                              void* d_out, int out_size) {
    const float* x       = (const float*)d_in[0];   // [8192, 256]
    const float* adj     = (const float*)d_in[1];   // [8192, 8192]
    const float* Ws      = (const float*)d_in[2];   // [4, 256, 64]
    const float* a_heads = (const float*)d_in[3];   // [4, 128]
    const float* W_out   = (const float*)d_in[4];   // [256, 121]
    const float* a_out   = (const float*)d_in[5];   // [242]
    float* out = (float*)d_out;                     // [8192, 121]

    float* dHcat;
    cudaGetSymbolAddress((void**)&dHcat, g_hcat);

    static cudaStream_t s_side = []() {
        cudaStream_t s; cudaStreamCreateWithFlags(&s, cudaStreamNonBlocking); return s;
    }();
    static cudaEvent_t ev_fork = []() {
        cudaEvent_t e; cudaEventCreateWithFlags(&e, cudaEventDisableTiming); return e;
    }();
    static cudaEvent_t ev_join = []() {
        cudaEvent_t e; cudaEventCreateWithFlags(&e, cudaEventDisableTiming); return e;
    }();

    // fork: CSR build (DRAM-bound) runs concurrently with GEMM1 (FMA-bound)
    cudaEventRecord(ev_fork, 0);
    cudaStreamWaitEvent(s_side, ev_fork, 0);
    build_csr<<<N_NODES / 8, 256, 0, s_side>>>(adj);
    cudaEventRecord(ev_join, s_side);

    // main stream: layer-1 GEMM with fused f1 epilogue + fp16 Wh store
    sgemm6<0><<<dim3(4, N_NODES / 64), 256>>>(x, Ws, a_heads);

    // join: aggregation needs both CSR and scores
    cudaStreamWaitEvent(0, ev_join, 0);
    layer1_agg<<<N_NODES / 4, 256>>>();

    // layer 2: GEMM with fused f2-partials epilogue + fp16 Wh2 store, then aggregate
    sgemm6<1><<<dim3(2, N_NODES / 64), 256>>>(dHcat, W_out, a_out);
    layer2_agg<<<N_NODES / 4, 256>>>(out);
}